// round 1
// baseline (speedup 1.0000x reference)
#include <cuda_runtime.h>
#include <math.h>

#define NMAX   50000
#define EMAX   800000
#define HDIM   64
#define NHEADS 4
#define FIN    128

// ---------------- scratch (device globals; no allocation allowed) ----------
__device__ int      g_flag;                  // 1 => edge_index is int64
__device__ int      g_row[EMAX];
__device__ int      g_col[EMAX];
__device__ int      g_indeg[NMAX];
__device__ float    g_dinv[NMAX];
__device__ float    g_h1  [NMAX*HDIM];       // x @ W1
__device__ float    g_acc1[NMAX*HDIM];       // GCN agg accumulator
__device__ float    g_hA  [NMAX*HDIM];       // post-GCN (relu)
__device__ float    g_hg  [NMAX*NHEADS*HDIM];// hA @ Wg
__device__ float    g_asrc[NMAX*NHEADS];
__device__ float    g_adst[NMAX*NHEADS];
__device__ unsigned g_emaxk[NMAX*NHEADS];    // encoded max keys
__device__ float    g_denom[NMAX*NHEADS];
__device__ float    g_invden[NMAX*NHEADS];
__device__ float    g_ex  [EMAX*NHEADS];
__device__ float    g_exself[NMAX*NHEADS];
__device__ float    g_acc2[NMAX*HDIM];       // GAT agg accumulator
__device__ float    g_hB  [NMAX*HDIM];       // post-GAT (relu)
__device__ float    g_acc3[NMAX*HDIM];       // SAGE agg accumulator
__device__ float    g_macc[NMAX*HDIM];       // SAGE mean agg

// ---------------- helpers --------------------------------------------------
__device__ __forceinline__ unsigned fenc(float f) {
    unsigned u = __float_as_uint(f);
    return (u & 0x80000000u) ? ~u : (u | 0x80000000u);
}
__device__ __forceinline__ float fdec(unsigned k) {
    unsigned u = (k & 0x80000000u) ? (k & 0x7fffffffu) : ~k;
    return __uint_as_float(u);
}
__device__ __forceinline__ float lrelu02(float x) { return x >= 0.f ? x : 0.2f * x; }

// ---------------- dtype detection ------------------------------------------
__global__ void detect_kernel(const unsigned* __restrict__ words) {
    __shared__ int nz;
    if (threadIdx.x == 0) nz = 0;
    __syncthreads();
    // If int64: odd 32-bit words are the zero high halves of values < 2^31.
    // If int32: odd words are random indices in [0, 50000) -> almost surely nonzero.
    unsigned w = words[threadIdx.x * 2 + 1];
    if (w != 0u) atomicAdd(&nz, 1);
    __syncthreads();
    if (threadIdx.x == 0) g_flag = (nz == 0) ? 1 : 0;
}

__global__ void convert_kernel(const void* __restrict__ eidx, int E) {
    int i = blockIdx.x * blockDim.x + threadIdx.x;
    if (i >= E) return;
    int r, c;
    if (g_flag) {
        const long long* p = (const long long*)eidx;
        r = (int)p[i]; c = (int)p[i + E];
    } else {
        const int* p = (const int*)eidx;
        r = p[i]; c = p[i + E];
    }
    g_row[i] = r; g_col[i] = c;
}

// ---------------- generic small-K GEMM  out[M,NC] = A[M,K] @ W[K,NC] --------
template<int K, int NC, bool BIAS, bool RELU, bool ACCUM>
__global__ __launch_bounds__(256) void gemm_kernel(
        const float* __restrict__ A, const float* __restrict__ W,
        const float* __restrict__ bias, float* __restrict__ out, int M) {
    constexpr int ROWS = 16;
    __shared__ float As[ROWS * K];
    int row0 = blockIdx.x * ROWS;
    for (int t = threadIdx.x; t < ROWS * K; t += blockDim.x) {
        int r = t / K, k = t - r * K;
        int gr = row0 + r;
        As[t] = (gr < M) ? A[(long)gr * K + k] : 0.f;
    }
    __syncthreads();
    constexpr int ITEMS = ROWS * (NC / 4);
    for (int t = threadIdx.x; t < ITEMS; t += blockDim.x) {
        int r = t / (NC / 4);
        int j = (t - r * (NC / 4)) * 4;
        int gr = row0 + r;
        if (gr >= M) continue;
        float4 acc = make_float4(0.f, 0.f, 0.f, 0.f);
        const float* as = As + r * K;
        #pragma unroll 8
        for (int k = 0; k < K; k++) {
            float a = as[k];
            float4 w = *(const float4*)(W + (long)k * NC + j);
            acc.x += a * w.x; acc.y += a * w.y; acc.z += a * w.z; acc.w += a * w.w;
        }
        if (BIAS) {
            acc.x += bias[j]; acc.y += bias[j + 1]; acc.z += bias[j + 2]; acc.w += bias[j + 3];
        }
        float* o = out + (long)gr * NC + j;
        if (ACCUM) {
            float4 p = *(const float4*)o;
            acc.x += p.x; acc.y += p.y; acc.z += p.z; acc.w += p.w;
        }
        if (RELU) {
            acc.x = fmaxf(acc.x, 0.f); acc.y = fmaxf(acc.y, 0.f);
            acc.z = fmaxf(acc.z, 0.f); acc.w = fmaxf(acc.w, 0.f);
        }
        *(float4*)o = acc;
    }
}

// ---------------- degree / dinv --------------------------------------------
__global__ void deg_kernel(int E) {
    int i = blockIdx.x * blockDim.x + threadIdx.x;
    if (i >= E) return;
    atomicAdd(&g_indeg[g_col[i]], 1);
}
__global__ void dinv_kernel(int N) {
    int i = blockIdx.x * blockDim.x + threadIdx.x;
    if (i >= N) return;
    g_dinv[i] = rsqrtf((float)(g_indeg[i] + 1));   // +1 for self loop
}

// ---------------- GCN -------------------------------------------------------
__global__ __launch_bounds__(256) void gcn_agg_kernel(int E) {
    int idx = blockIdx.x * blockDim.x + threadIdx.x;
    if (idx >= E * HDIM) return;
    int e = idx >> 6, c = idx & 63;
    int r = g_row[e], cl = g_col[e];
    float v = g_dinv[r] * g_dinv[cl] * g_h1[r * HDIM + c];
    atomicAdd(&g_acc1[cl * HDIM + c], v);
}
__global__ void gcn_finish_kernel(const float* __restrict__ b1, int N) {
    int idx = blockIdx.x * blockDim.x + threadIdx.x;
    if (idx >= N * HDIM) return;
    int n = idx >> 6, c = idx & 63;
    float di = g_dinv[n];
    float v = g_acc1[idx] + di * di * g_h1[idx] + b1[c];
    g_hA[idx] = fmaxf(v, 0.f);
}

// ---------------- GAT -------------------------------------------------------
__global__ void att_kernel(const float* __restrict__ att_src,
                           const float* __restrict__ att_dst, int N) {
    int warp = (blockIdx.x * blockDim.x + threadIdx.x) >> 5;
    int lane = threadIdx.x & 31;
    if (warp >= N) return;
    const float* hg = g_hg + (long)warp * (NHEADS * HDIM);
    #pragma unroll
    for (int h = 0; h < NHEADS; h++) {
        float v1 = hg[h * HDIM + lane], v2 = hg[h * HDIM + 32 + lane];
        float s = v1 * att_src[h * HDIM + lane] + v2 * att_src[h * HDIM + 32 + lane];
        float d = v1 * att_dst[h * HDIM + lane] + v2 * att_dst[h * HDIM + 32 + lane];
        #pragma unroll
        for (int o = 16; o; o >>= 1) {
            s += __shfl_xor_sync(0xffffffffu, s, o);
            d += __shfl_xor_sync(0xffffffffu, d, o);
        }
        if (lane == 0) { g_asrc[warp * NHEADS + h] = s; g_adst[warp * NHEADS + h] = d; }
    }
}

__global__ void gat_max_kernel(int E, int N) {
    int idx = blockIdx.x * blockDim.x + threadIdx.x;
    int total = (E + N) * NHEADS;
    if (idx >= total) return;
    int h = idx & 3, t = idx >> 2;
    int r, c;
    if (t < E) { r = g_row[t]; c = g_col[t]; } else { r = t - E; c = r; }
    float e = lrelu02(g_asrc[r * NHEADS + h] + g_adst[c * NHEADS + h]);
    atomicMax(&g_emaxk[c * NHEADS + h], fenc(e));
}

__global__ void gat_denom_kernel(int E, int N) {
    int idx = blockIdx.x * blockDim.x + threadIdx.x;
    int total = (E + N) * NHEADS;
    if (idx >= total) return;
    int h = idx & 3, t = idx >> 2;
    int r, c;
    if (t < E) { r = g_row[t]; c = g_col[t]; } else { r = t - E; c = r; }
    float e = lrelu02(g_asrc[r * NHEADS + h] + g_adst[c * NHEADS + h]);
    float ex = expf(e - fdec(g_emaxk[c * NHEADS + h]));
    if (t < E) g_ex[t * NHEADS + h] = ex;
    else       g_exself[r * NHEADS + h] = ex;
    atomicAdd(&g_denom[c * NHEADS + h], ex);
}

__global__ void invden_kernel(int N) {
    int i = blockIdx.x * blockDim.x + threadIdx.x;
    if (i >= N * NHEADS) return;
    g_invden[i] = 1.f / g_denom[i];
}

__global__ __launch_bounds__(256) void gat_agg_kernel(int E) {
    int idx = blockIdx.x * blockDim.x + threadIdx.x;
    if (idx >= E * HDIM) return;
    int e = idx >> 6, c = idx & 63;
    int r = g_row[e], cl = g_col[e];
    float4 ex  = *(const float4*)&g_ex[e * NHEADS];
    float4 inv = *(const float4*)&g_invden[cl * NHEADS];
    const float* hg = g_hg + (long)r * (NHEADS * HDIM) + c;
    float s = ex.x * inv.x * hg[0]
            + ex.y * inv.y * hg[HDIM]
            + ex.z * inv.z * hg[2 * HDIM]
            + ex.w * inv.w * hg[3 * HDIM];
    atomicAdd(&g_acc2[cl * HDIM + c], s);
}

__global__ void gat_finish_kernel(const float* __restrict__ bg, int N) {
    int idx = blockIdx.x * blockDim.x + threadIdx.x;
    if (idx >= N * HDIM) return;
    int n = idx >> 6, c = idx & 63;
    float4 ex  = *(const float4*)&g_exself[n * NHEADS];
    float4 inv = *(const float4*)&g_invden[n * NHEADS];
    const float* hg = g_hg + (long)n * (NHEADS * HDIM) + c;
    float s = g_acc2[idx]
            + ex.x * inv.x * hg[0]
            + ex.y * inv.y * hg[HDIM]
            + ex.z * inv.z * hg[2 * HDIM]
            + ex.w * inv.w * hg[3 * HDIM];
    g_hB[idx] = fmaxf(0.25f * s + bg[c], 0.f);
}

// ---------------- SAGE ------------------------------------------------------
__global__ __launch_bounds__(256) void sage_agg_kernel(int E) {
    int idx = blockIdx.x * blockDim.x + threadIdx.x;
    if (idx >= E * HDIM) return;
    int e = idx >> 6, c = idx & 63;
    atomicAdd(&g_acc3[g_col[e] * HDIM + c], g_hB[g_row[e] * HDIM + c]);
}
__global__ void sage_scale_kernel(int N) {
    int idx = blockIdx.x * blockDim.x + threadIdx.x;
    if (idx >= N * HDIM) return;
    int n = idx >> 6;
    float d = fmaxf((float)g_indeg[n], 1.f);
    g_macc[idx] = g_acc3[idx] / d;
}

// ---------------- heads -----------------------------------------------------
__global__ void heads_kernel(const float* __restrict__ emb,
        const float* __restrict__ a1w, const float* __restrict__ a1b,
        const float* __restrict__ a2w, const float* __restrict__ a2b,
        const float* __restrict__ r1w, const float* __restrict__ r1b,
        const float* __restrict__ r2w, const float* __restrict__ r2b,
        float* __restrict__ anomaly, float* __restrict__ risk, int N) {
    int warp = (blockIdx.x * blockDim.x + threadIdx.x) >> 5;
    int lane = threadIdx.x & 31;
    if (warp >= N) return;
    const float* e = emb + (long)warp * HDIM;
    float sa = a1b[lane], sr = r1b[lane];
    #pragma unroll 8
    for (int k = 0; k < HDIM; k++) {
        float ev = e[k];
        sa += ev * a1w[k * 32 + lane];
        sr += ev * r1w[k * 32 + lane];
    }
    sa = fmaxf(sa, 0.f) * a2w[lane];
    sr = fmaxf(sr, 0.f) * r2w[lane];
    #pragma unroll
    for (int o = 16; o; o >>= 1) {
        sa += __shfl_xor_sync(0xffffffffu, sa, o);
        sr += __shfl_xor_sync(0xffffffffu, sr, o);
    }
    if (lane == 0) {
        anomaly[warp] = 1.f / (1.f + expf(-(sa + a2b[0])));
        risk[warp]    = 1.f / (1.f + expf(-(sr + r2b[0])));
    }
}

// ---------------- launch ----------------------------------------------------
extern "C" void kernel_launch(void* const* d_in, const int* in_sizes, int n_in,
                              void* d_out, int out_size) {
    const float* x    = (const float*)d_in[0];
    const void*  eidx = d_in[1];
    const float* W1   = (const float*)d_in[2];
    const float* b1   = (const float*)d_in[3];
    const float* Wg   = (const float*)d_in[4];
    // disambiguate (att_src, att_dst, bg) vs (bg, att_src, att_dst)
    const float *att_src, *att_dst, *bg;
    if (in_sizes[5] == NHEADS * HDIM) {        // dict order
        att_src = (const float*)d_in[5];
        att_dst = (const float*)d_in[6];
        bg      = (const float*)d_in[7];
    } else {                                    // signature order
        bg      = (const float*)d_in[5];
        att_src = (const float*)d_in[6];
        att_dst = (const float*)d_in[7];
    }
    const float* Wl  = (const float*)d_in[8];
    const float* bl  = (const float*)d_in[9];
    const float* Wr  = (const float*)d_in[10];
    const float* a1w = (const float*)d_in[11];
    const float* a1b = (const float*)d_in[12];
    const float* a2w = (const float*)d_in[13];
    const float* a2b = (const float*)d_in[14];
    const float* r1w = (const float*)d_in[15];
    const float* r1b = (const float*)d_in[16];
    const float* r2w = (const float*)d_in[17];
    const float* r2b = (const float*)d_in[18];

    int N = in_sizes[0] / FIN;
    int E = in_sizes[1] / 2;

    float* out_emb = (float*)d_out;
    float* out_an  = out_emb + (long)N * HDIM;
    float* out_rk  = out_an + N;

    // zero accumulators
    void* p;
    cudaGetSymbolAddress(&p, g_indeg);  cudaMemsetAsync(p, 0, (size_t)N * 4);
    cudaGetSymbolAddress(&p, g_acc1);   cudaMemsetAsync(p, 0, (size_t)N * HDIM * 4);
    cudaGetSymbolAddress(&p, g_acc2);   cudaMemsetAsync(p, 0, (size_t)N * HDIM * 4);
    cudaGetSymbolAddress(&p, g_acc3);   cudaMemsetAsync(p, 0, (size_t)N * HDIM * 4);
    cudaGetSymbolAddress(&p, g_emaxk);  cudaMemsetAsync(p, 0, (size_t)N * NHEADS * 4);
    cudaGetSymbolAddress(&p, g_denom);  cudaMemsetAsync(p, 0, (size_t)N * NHEADS * 4);

    detect_kernel<<<1, 256>>>((const unsigned*)eidx);
    convert_kernel<<<(E + 255) / 256, 256>>>(eidx, E);

    // GCN
    {
        void* h1; cudaGetSymbolAddress(&h1, g_h1);
        gemm_kernel<FIN, HDIM, false, false, false><<<(N + 15) / 16, 256>>>(
            x, W1, nullptr, (float*)h1, N);
    }
    deg_kernel<<<(E + 255) / 256, 256>>>(E);
    dinv_kernel<<<(N + 255) / 256, 256>>>(N);
    gcn_agg_kernel<<<(E * HDIM + 255) / 256, 256>>>(E);
    gcn_finish_kernel<<<(N * HDIM + 255) / 256, 256>>>(b1, N);

    // GAT
    {
        void* hA; cudaGetSymbolAddress(&hA, g_hA);
        void* hg; cudaGetSymbolAddress(&hg, g_hg);
        gemm_kernel<HDIM, NHEADS * HDIM, false, false, false><<<(N + 15) / 16, 256>>>(
            (const float*)hA, Wg, nullptr, (float*)hg, N);
    }
    att_kernel<<<(N * 32 + 255) / 256, 256>>>(att_src, att_dst, N);
    gat_max_kernel<<<((E + N) * NHEADS + 255) / 256, 256>>>(E, N);
    gat_denom_kernel<<<((E + N) * NHEADS + 255) / 256, 256>>>(E, N);
    invden_kernel<<<(N * NHEADS + 255) / 256, 256>>>(N);
    gat_agg_kernel<<<(E * HDIM + 255) / 256, 256>>>(E);
    gat_finish_kernel<<<(N * HDIM + 255) / 256, 256>>>(bg, N);

    // SAGE
    sage_agg_kernel<<<(E * HDIM + 255) / 256, 256>>>(E);
    sage_scale_kernel<<<(N * HDIM + 255) / 256, 256>>>(N);
    {
        void* macc; cudaGetSymbolAddress(&macc, g_macc);
        void* hB;   cudaGetSymbolAddress(&hB, g_hB);
        gemm_kernel<HDIM, HDIM, true, false, false><<<(N + 15) / 16, 256>>>(
            (const float*)macc, Wl, bl, out_emb, N);
        gemm_kernel<HDIM, HDIM, false, false, true><<<(N + 15) / 16, 256>>>(
            (const float*)hB, Wr, nullptr, out_emb, N);
    }

    // heads
    heads_kernel<<<(N * 32 + 255) / 256, 256>>>(
        out_emb, a1w, a1b, a2w, a2b, r1w, r1b, r2w, r2b, out_an, out_rk, N);
}

// round 2
// speedup vs baseline: 1.6003x; 1.6003x over previous
#include <cuda_runtime.h>
#include <math.h>

#define NMAX   50000
#define EMAX   800000
#define HDIM   64
#define NHEADS 4
#define FIN    128

// ---------------- scratch (device globals; no allocation allowed) ----------
__device__ int      g_flag;                  // 1 => edge_index is int64
__device__ int      g_row[EMAX];
__device__ int      g_col[EMAX];
__device__ int      g_indeg[NMAX];
__device__ int      g_rowptr[NMAX + 1];
__device__ int      g_cursor[NMAX];
__device__ int      g_csrc[EMAX];            // CSR: src node per in-edge, grouped by dst
__device__ float    g_dinv[NMAX];
__device__ float    g_h1  [NMAX*HDIM];       // x @ W1
__device__ float    g_hA  [NMAX*HDIM];       // post-GCN (relu)
__device__ float    g_hg  [NMAX*NHEADS*HDIM];// hA @ Wg  (layout [n][h][c])
__device__ float    g_asrc[NMAX*NHEADS];
__device__ float    g_adst[NMAX*NHEADS];
__device__ float    g_hB  [NMAX*HDIM];       // post-GAT (relu)
__device__ float    g_macc[NMAX*HDIM];       // SAGE mean agg

__device__ __forceinline__ float lrelu02(float x) { return x >= 0.f ? x : 0.2f * x; }

// ---------------- dtype detection ------------------------------------------
__global__ void detect_kernel(const unsigned* __restrict__ words) {
    __shared__ int nz;
    if (threadIdx.x == 0) nz = 0;
    __syncthreads();
    unsigned w = words[threadIdx.x * 2 + 1];
    if (w != 0u) atomicAdd(&nz, 1);
    __syncthreads();
    if (threadIdx.x == 0) g_flag = (nz == 0) ? 1 : 0;
}

// convert edge index to int32 and accumulate in-degree (over original edges)
__global__ void convert_deg_kernel(const void* __restrict__ eidx, int E) {
    int i = blockIdx.x * blockDim.x + threadIdx.x;
    if (i >= E) return;
    int r, c;
    if (g_flag) {
        const long long* p = (const long long*)eidx;
        r = (int)p[i]; c = (int)p[i + E];
    } else {
        const int* p = (const int*)eidx;
        r = p[i]; c = p[i + E];
    }
    g_row[i] = r; g_col[i] = c;
    atomicAdd(&g_indeg[c], 1);
}

// exclusive scan of g_indeg -> g_rowptr  (single block, 1024 threads)
__global__ void scan_kernel(int N) {
    __shared__ int sums[1024];
    int tid = threadIdx.x;
    int chunk = (N + 1023) / 1024;
    int b = tid * chunk, e = min(b + chunk, N);
    int s = 0;
    for (int i = b; i < e; i++) s += g_indeg[i];
    sums[tid] = s;
    __syncthreads();
    // inclusive Hillis-Steele
    for (int off = 1; off < 1024; off <<= 1) {
        int v = (tid >= off) ? sums[tid - off] : 0;
        __syncthreads();
        sums[tid] += v;
        __syncthreads();
    }
    int run = (tid > 0) ? sums[tid - 1] : 0;
    for (int i = b; i < e; i++) { g_rowptr[i] = run; run += g_indeg[i]; }
    if (tid == 1023) g_rowptr[N] = sums[1023];
}

__global__ void fill_kernel(int E) {
    int i = blockIdx.x * blockDim.x + threadIdx.x;
    if (i >= E) return;
    int c = g_col[i];
    int pos = g_rowptr[c] + atomicAdd(&g_cursor[c], 1);
    g_csrc[pos] = g_row[i];
}

__global__ void dinv_kernel(int N) {
    int i = blockIdx.x * blockDim.x + threadIdx.x;
    if (i >= N) return;
    g_dinv[i] = rsqrtf((float)(g_indeg[i] + 1));   // +1 for self loop
}

// ---------------- generic small-K GEMM  out[M,NC] = A[M,K] @ W[K,NC] --------
template<int K, int NC, bool BIAS, bool RELU>
__global__ __launch_bounds__(256) void gemm_kernel(
        const float* __restrict__ A, const float* __restrict__ W,
        const float* __restrict__ bias, float* __restrict__ out, int M) {
    constexpr int ROWS = 16;
    __shared__ float As[ROWS * K];
    int row0 = blockIdx.x * ROWS;
    for (int t = threadIdx.x; t < ROWS * K; t += blockDim.x) {
        int r = t / K, k = t - r * K;
        int gr = row0 + r;
        As[t] = (gr < M) ? A[(long)gr * K + k] : 0.f;
    }
    __syncthreads();
    constexpr int ITEMS = ROWS * (NC / 4);
    for (int t = threadIdx.x; t < ITEMS; t += blockDim.x) {
        int r = t / (NC / 4);
        int j = (t - r * (NC / 4)) * 4;
        int gr = row0 + r;
        if (gr >= M) continue;
        float4 acc = make_float4(0.f, 0.f, 0.f, 0.f);
        const float* as = As + r * K;
        #pragma unroll 8
        for (int k = 0; k < K; k++) {
            float a = as[k];
            float4 w = *(const float4*)(W + (long)k * NC + j);
            acc.x += a * w.x; acc.y += a * w.y; acc.z += a * w.z; acc.w += a * w.w;
        }
        if (BIAS) {
            acc.x += bias[j]; acc.y += bias[j + 1]; acc.z += bias[j + 2]; acc.w += bias[j + 3];
        }
        if (RELU) {
            acc.x = fmaxf(acc.x, 0.f); acc.y = fmaxf(acc.y, 0.f);
            acc.z = fmaxf(acc.z, 0.f); acc.w = fmaxf(acc.w, 0.f);
        }
        *(float4*)(out + (long)gr * NC + j) = acc;
    }
}

// dual-A GEMM: out = A1@W1v + A2@W2v + bias   (K = NC = 64)
__global__ __launch_bounds__(256) void gemm2_kernel(
        const float* __restrict__ A1, const float* __restrict__ W1v,
        const float* __restrict__ A2, const float* __restrict__ W2v,
        const float* __restrict__ bias, float* __restrict__ out, int M) {
    constexpr int K = 64, NC = 64, ROWS = 16;
    __shared__ float As1[ROWS * K];
    __shared__ float As2[ROWS * K];
    int row0 = blockIdx.x * ROWS;
    for (int t = threadIdx.x; t < ROWS * K; t += blockDim.x) {
        int r = t / K, k = t - r * K;
        int gr = row0 + r;
        As1[t] = (gr < M) ? A1[(long)gr * K + k] : 0.f;
        As2[t] = (gr < M) ? A2[(long)gr * K + k] : 0.f;
    }
    __syncthreads();
    constexpr int ITEMS = ROWS * (NC / 4);
    for (int t = threadIdx.x; t < ITEMS; t += blockDim.x) {
        int r = t / (NC / 4);
        int j = (t - r * (NC / 4)) * 4;
        int gr = row0 + r;
        if (gr >= M) continue;
        float4 acc = make_float4(bias[j], bias[j + 1], bias[j + 2], bias[j + 3]);
        const float* a1 = As1 + r * K;
        const float* a2 = As2 + r * K;
        #pragma unroll 8
        for (int k = 0; k < K; k++) {
            float av1 = a1[k], av2 = a2[k];
            float4 w1 = *(const float4*)(W1v + (long)k * NC + j);
            float4 w2 = *(const float4*)(W2v + (long)k * NC + j);
            acc.x += av1 * w1.x + av2 * w2.x;
            acc.y += av1 * w1.y + av2 * w2.y;
            acc.z += av1 * w1.z + av2 * w2.z;
            acc.w += av1 * w1.w + av2 * w2.w;
        }
        *(float4*)(out + (long)gr * NC + j) = acc;
    }
}

// ---------------- GCN node gather (fused norm + self-loop + bias + relu) ----
__global__ __launch_bounds__(64) void gcn_node_kernel(const float* __restrict__ b1) {
    int n = blockIdx.x;
    int c = threadIdx.x;
    int beg = g_rowptr[n], end = g_rowptr[n + 1];
    float acc0 = 0.f, acc1 = 0.f;
    int j = beg;
    for (; j + 1 < end; j += 2) {
        int s0 = g_csrc[j], s1 = g_csrc[j + 1];
        acc0 += g_dinv[s0] * g_h1[s0 * HDIM + c];
        acc1 += g_dinv[s1] * g_h1[s1 * HDIM + c];
    }
    if (j < end) {
        int s0 = g_csrc[j];
        acc0 += g_dinv[s0] * g_h1[s0 * HDIM + c];
    }
    float dn = g_dinv[n];
    float v = dn * (acc0 + acc1) + dn * dn * g_h1[n * HDIM + c] + b1[c];
    g_hA[n * HDIM + c] = fmaxf(v, 0.f);
}

// ---------------- GAT per-node attention scores ------------------------------
__global__ void att_kernel(const float* __restrict__ att_src,
                           const float* __restrict__ att_dst, int N) {
    int warp = (blockIdx.x * blockDim.x + threadIdx.x) >> 5;
    int lane = threadIdx.x & 31;
    if (warp >= N) return;
    const float* hg = g_hg + (long)warp * (NHEADS * HDIM);
    #pragma unroll
    for (int h = 0; h < NHEADS; h++) {
        float v1 = hg[h * HDIM + lane], v2 = hg[h * HDIM + 32 + lane];
        float s = v1 * att_src[h * HDIM + lane] + v2 * att_src[h * HDIM + 32 + lane];
        float d = v1 * att_dst[h * HDIM + lane] + v2 * att_dst[h * HDIM + 32 + lane];
        #pragma unroll
        for (int o = 16; o; o >>= 1) {
            s += __shfl_xor_sync(0xffffffffu, s, o);
            d += __shfl_xor_sync(0xffffffffu, d, o);
        }
        if (lane == 0) { g_asrc[warp * NHEADS + h] = s; g_adst[warp * NHEADS + h] = d; }
    }
}

// ---------------- GAT node: softmax over in-edges + weighted gather ----------
__global__ __launch_bounds__(64) void gat_node_kernel(const float* __restrict__ bg) {
    __shared__ float smax[NHEADS];
    __shared__ float sinvden[NHEADS];
    __shared__ float salpha_self[NHEADS];
    __shared__ float redbuf[2 * NHEADS];
    __shared__ float s_alpha[16 * NHEADS];
    __shared__ int   s_src[16];

    int n = blockIdx.x;
    int tid = threadIdx.x;
    int lane = tid & 31, wid = tid >> 5;
    int beg = g_rowptr[n], end = g_rowptr[n + 1];

    float4 ad = *(const float4*)&g_adst[n * NHEADS];
    float4 asn = *(const float4*)&g_asrc[n * NHEADS];
    float eself[NHEADS] = {
        lrelu02(asn.x + ad.x), lrelu02(asn.y + ad.y),
        lrelu02(asn.z + ad.z), lrelu02(asn.w + ad.w) };

    // pass 1: max per head (self term included via init)
    float m[NHEADS] = { eself[0], eself[1], eself[2], eself[3] };
    for (int j = beg + tid; j < end; j += 64) {
        int s = g_csrc[j];
        float4 as = *(const float4*)&g_asrc[s * NHEADS];
        m[0] = fmaxf(m[0], lrelu02(as.x + ad.x));
        m[1] = fmaxf(m[1], lrelu02(as.y + ad.y));
        m[2] = fmaxf(m[2], lrelu02(as.z + ad.z));
        m[3] = fmaxf(m[3], lrelu02(as.w + ad.w));
    }
    #pragma unroll
    for (int o = 16; o; o >>= 1)
        #pragma unroll
        for (int h = 0; h < NHEADS; h++)
            m[h] = fmaxf(m[h], __shfl_xor_sync(0xffffffffu, m[h], o));
    if (lane == 0)
        #pragma unroll
        for (int h = 0; h < NHEADS; h++) redbuf[wid * NHEADS + h] = m[h];
    __syncthreads();
    if (tid < NHEADS) smax[tid] = fmaxf(redbuf[tid], redbuf[NHEADS + tid]);
    __syncthreads();

    // pass 2: denominator per head
    float d[NHEADS] = { 0.f, 0.f, 0.f, 0.f };
    for (int j = beg + tid; j < end; j += 64) {
        int s = g_csrc[j];
        float4 as = *(const float4*)&g_asrc[s * NHEADS];
        d[0] += __expf(lrelu02(as.x + ad.x) - smax[0]);
        d[1] += __expf(lrelu02(as.y + ad.y) - smax[1]);
        d[2] += __expf(lrelu02(as.z + ad.z) - smax[2]);
        d[3] += __expf(lrelu02(as.w + ad.w) - smax[3]);
    }
    #pragma unroll
    for (int o = 16; o; o >>= 1)
        #pragma unroll
        for (int h = 0; h < NHEADS; h++)
            d[h] += __shfl_xor_sync(0xffffffffu, d[h], o);
    if (lane == 0)
        #pragma unroll
        for (int h = 0; h < NHEADS; h++) redbuf[wid * NHEADS + h] = d[h];
    __syncthreads();
    if (tid < NHEADS) {
        float exs = __expf(eself[tid] - smax[tid]);
        float den = redbuf[tid] + redbuf[NHEADS + tid] + exs;
        float inv = 1.f / den;
        sinvden[tid] = inv;
        salpha_self[tid] = exs * inv;
    }
    __syncthreads();

    // pass 3: chunked alpha staging + weighted gather; c = tid
    int c = tid;
    float acc = 0.f;
    for (int base = beg; base < end; base += 16) {
        int cnt = min(16, end - base);
        if (tid < cnt * NHEADS) {
            int jj = tid >> 2, h = tid & 3;
            int s = g_csrc[base + jj];
            float av = g_asrc[s * NHEADS + h];
            float dv = ((const float*)&ad)[h];
            float e = lrelu02(av + dv);
            s_alpha[jj * NHEADS + h] = __expf(e - smax[h]) * sinvden[h];
            if (h == 0) s_src[jj] = s;
        }
        __syncthreads();
        for (int jj = 0; jj < cnt; jj++) {
            int s = s_src[jj];
            const float* hgp = g_hg + (long)s * (NHEADS * HDIM) + c;
            acc += s_alpha[jj * NHEADS + 0] * hgp[0]
                 + s_alpha[jj * NHEADS + 1] * hgp[HDIM]
                 + s_alpha[jj * NHEADS + 2] * hgp[2 * HDIM]
                 + s_alpha[jj * NHEADS + 3] * hgp[3 * HDIM];
        }
        __syncthreads();
    }
    // self contribution
    {
        const float* hgp = g_hg + (long)n * (NHEADS * HDIM) + c;
        acc += salpha_self[0] * hgp[0]
             + salpha_self[1] * hgp[HDIM]
             + salpha_self[2] * hgp[2 * HDIM]
             + salpha_self[3] * hgp[3 * HDIM];
    }
    g_hB[n * HDIM + c] = fmaxf(0.25f * acc + bg[c], 0.f);
}

// ---------------- SAGE node mean gather -------------------------------------
__global__ __launch_bounds__(64) void sage_node_kernel() {
    int n = blockIdx.x;
    int c = threadIdx.x;
    int beg = g_rowptr[n], end = g_rowptr[n + 1];
    float acc0 = 0.f, acc1 = 0.f;
    int j = beg;
    for (; j + 1 < end; j += 2) {
        int s0 = g_csrc[j], s1 = g_csrc[j + 1];
        acc0 += g_hB[s0 * HDIM + c];
        acc1 += g_hB[s1 * HDIM + c];
    }
    if (j < end) acc0 += g_hB[g_csrc[j] * HDIM + c];
    float inv = 1.f / fmaxf((float)(end - beg), 1.f);
    g_macc[n * HDIM + c] = (acc0 + acc1) * inv;
}

// ---------------- heads -----------------------------------------------------
__global__ void heads_kernel(const float* __restrict__ emb,
        const float* __restrict__ a1w, const float* __restrict__ a1b,
        const float* __restrict__ a2w, const float* __restrict__ a2b,
        const float* __restrict__ r1w, const float* __restrict__ r1b,
        const float* __restrict__ r2w, const float* __restrict__ r2b,
        float* __restrict__ anomaly, float* __restrict__ risk, int N) {
    int warp = (blockIdx.x * blockDim.x + threadIdx.x) >> 5;
    int lane = threadIdx.x & 31;
    if (warp >= N) return;
    const float* e = emb + (long)warp * HDIM;
    float sa = a1b[lane], sr = r1b[lane];
    #pragma unroll 8
    for (int k = 0; k < HDIM; k++) {
        float ev = e[k];
        sa += ev * a1w[k * 32 + lane];
        sr += ev * r1w[k * 32 + lane];
    }
    sa = fmaxf(sa, 0.f) * a2w[lane];
    sr = fmaxf(sr, 0.f) * r2w[lane];
    #pragma unroll
    for (int o = 16; o; o >>= 1) {
        sa += __shfl_xor_sync(0xffffffffu, sa, o);
        sr += __shfl_xor_sync(0xffffffffu, sr, o);
    }
    if (lane == 0) {
        anomaly[warp] = 1.f / (1.f + __expf(-(sa + a2b[0])));
        risk[warp]    = 1.f / (1.f + __expf(-(sr + r2b[0])));
    }
}

// ---------------- launch ----------------------------------------------------
extern "C" void kernel_launch(void* const* d_in, const int* in_sizes, int n_in,
                              void* d_out, int out_size) {
    const float* x    = (const float*)d_in[0];
    const void*  eidx = d_in[1];
    const float* W1   = (const float*)d_in[2];
    const float* b1   = (const float*)d_in[3];
    const float* Wg   = (const float*)d_in[4];
    const float *att_src, *att_dst, *bg;
    if (in_sizes[5] == NHEADS * HDIM) {        // dict order
        att_src = (const float*)d_in[5];
        att_dst = (const float*)d_in[6];
        bg      = (const float*)d_in[7];
    } else {                                    // signature order
        bg      = (const float*)d_in[5];
        att_src = (const float*)d_in[6];
        att_dst = (const float*)d_in[7];
    }
    const float* Wl  = (const float*)d_in[8];
    const float* bl  = (const float*)d_in[9];
    const float* Wr  = (const float*)d_in[10];
    const float* a1w = (const float*)d_in[11];
    const float* a1b = (const float*)d_in[12];
    const float* a2w = (const float*)d_in[13];
    const float* a2b = (const float*)d_in[14];
    const float* r1w = (const float*)d_in[15];
    const float* r1b = (const float*)d_in[16];
    const float* r2w = (const float*)d_in[17];
    const float* r2b = (const float*)d_in[18];

    int N = in_sizes[0] / FIN;
    int E = in_sizes[1] / 2;

    float* out_emb = (float*)d_out;
    float* out_an  = out_emb + (long)N * HDIM;
    float* out_rk  = out_an + N;

    void* p;
    cudaGetSymbolAddress(&p, g_indeg);  cudaMemsetAsync(p, 0, (size_t)N * 4);
    cudaGetSymbolAddress(&p, g_cursor); cudaMemsetAsync(p, 0, (size_t)N * 4);

    detect_kernel<<<1, 256>>>((const unsigned*)eidx);
    convert_deg_kernel<<<(E + 255) / 256, 256>>>(eidx, E);
    scan_kernel<<<1, 1024>>>(N);
    fill_kernel<<<(E + 255) / 256, 256>>>(E);
    dinv_kernel<<<(N + 255) / 256, 256>>>(N);

    // GCN
    {
        void* h1; cudaGetSymbolAddress(&h1, g_h1);
        gemm_kernel<FIN, HDIM, false, false><<<(N + 15) / 16, 256>>>(
            x, W1, nullptr, (float*)h1, N);
    }
    gcn_node_kernel<<<N, 64>>>(b1);

    // GAT
    {
        void* hA; cudaGetSymbolAddress(&hA, g_hA);
        void* hg; cudaGetSymbolAddress(&hg, g_hg);
        gemm_kernel<HDIM, NHEADS * HDIM, false, false><<<(N + 15) / 16, 256>>>(
            (const float*)hA, Wg, nullptr, (float*)hg, N);
    }
    att_kernel<<<(N * 32 + 255) / 256, 256>>>(att_src, att_dst, N);
    gat_node_kernel<<<N, 64>>>(bg);

    // SAGE
    sage_node_kernel<<<N, 64>>>();
    {
        void* macc; cudaGetSymbolAddress(&macc, g_macc);
        void* hB;   cudaGetSymbolAddress(&hB, g_hB);
        gemm2_kernel<<<(N + 15) / 16, 256>>>(
            (const float*)macc, Wl, (const float*)hB, Wr, bl, out_emb, N);
    }

    // heads
    heads_kernel<<<(N * 32 + 255) / 256, 256>>>(
        out_emb, a1w, a1b, a2w, a2b, r1w, r1b, r2w, r2b, out_an, out_rk, N);
}

// round 4
// speedup vs baseline: 1.8533x; 1.1581x over previous
#include <cuda_runtime.h>
#include <math.h>

#define NMAX   50000
#define EMAX   800000
#define HDIM   64
#define NHEADS 4
#define FIN    128

// ---------------- scratch (device globals; no allocation allowed) ----------
__device__ int      g_flag;                  // 1 => edge_index is int64
__device__ int      g_row[EMAX];
__device__ int      g_col[EMAX];
__device__ int      g_indeg[NMAX];
__device__ int      g_rowptr[NMAX + 1];
__device__ int      g_cursor[NMAX];
__device__ int      g_csrc[EMAX];            // CSR: src node per in-edge, grouped by dst
__device__ float    g_dinv[NMAX];
__device__ float    g_h1  [NMAX*HDIM];       // x @ W1
__device__ float    g_hA  [NMAX*HDIM];       // post-GCN (relu)
__device__ float    g_hg  [NMAX*NHEADS*HDIM];// hA @ Wg  (layout [n][h][c])
__device__ float    g_asrc[NMAX*NHEADS];
__device__ float    g_adst[NMAX*NHEADS];
__device__ float    g_hB  [NMAX*HDIM];       // post-GAT (relu)
__device__ float    g_macc[NMAX*HDIM];       // SAGE mean agg

__device__ __forceinline__ float lrelu02(float x) { return x >= 0.f ? x : 0.2f * x; }

// ---------------- dtype detection ------------------------------------------
__global__ void detect_kernel(const unsigned* __restrict__ words) {
    __shared__ int nz;
    if (threadIdx.x == 0) nz = 0;
    __syncthreads();
    unsigned w = words[threadIdx.x * 2 + 1];
    if (w != 0u) atomicAdd(&nz, 1);
    __syncthreads();
    if (threadIdx.x == 0) g_flag = (nz == 0) ? 1 : 0;
}

// convert edge index to int32 and accumulate in-degree
__global__ void convert_deg_kernel(const void* __restrict__ eidx, int E) {
    int i = blockIdx.x * blockDim.x + threadIdx.x;
    if (i >= E) return;
    int r, c;
    if (g_flag) {
        const long long* p = (const long long*)eidx;
        r = (int)p[i]; c = (int)p[i + E];
    } else {
        const int* p = (const int*)eidx;
        r = p[i]; c = p[i + E];
    }
    g_row[i] = r; g_col[i] = c;
    atomicAdd(&g_indeg[c], 1);
}

// exclusive scan of g_indeg -> g_rowptr; also writes g_dinv
__global__ void scan_kernel(int N) {
    __shared__ int sums[1024];
    int tid = threadIdx.x;
    int chunk = (N + 1023) / 1024;
    int b = tid * chunk, e = min(b + chunk, N);
    int s = 0;
    for (int i = b; i < e; i++) s += g_indeg[i];
    sums[tid] = s;
    __syncthreads();
    for (int off = 1; off < 1024; off <<= 1) {
        int v = (tid >= off) ? sums[tid - off] : 0;
        __syncthreads();
        sums[tid] += v;
        __syncthreads();
    }
    int run = (tid > 0) ? sums[tid - 1] : 0;
    for (int i = b; i < e; i++) {
        int d = g_indeg[i];
        g_rowptr[i] = run; run += d;
        g_dinv[i] = rsqrtf((float)(d + 1));
    }
    if (tid == 1023) g_rowptr[N] = sums[1023];
}

__global__ void fill_kernel(int E) {
    int i = blockIdx.x * blockDim.x + threadIdx.x;
    if (i >= E) return;
    int c = g_col[i];
    int pos = g_rowptr[c] + atomicAdd(&g_cursor[c], 1);
    g_csrc[pos] = g_row[i];
}

// ---------------- register-tiled GEMM: out[M,NC] = A[M,K] @ W[K,NC] ---------
// 64x64 output tile per block, 256 threads, 4x4 per thread, K chunked by 64.
template<int K, bool BIAS, bool RELU>
__global__ __launch_bounds__(256) void gemm_tile_kernel(
        const float* __restrict__ A, const float* __restrict__ W,
        const float* __restrict__ bias, float* __restrict__ out,
        int M, int NC) {
    __shared__ float As[64 * 65];   // [k][row], pad 65 to dodge bank conflicts
    __shared__ float Ws[64 * 64];   // [k][col]
    int row0 = blockIdx.x * 64;
    int col0 = blockIdx.y * 64;
    int tx = threadIdx.x & 15, ty = threadIdx.x >> 4;
    float acc[4][4] = {};

    for (int k0 = 0; k0 < K; k0 += 64) {
        // stage A transposed
        #pragma unroll
        for (int i = 0; i < 4; i++) {
            int idx = threadIdx.x * 4 + i;     // 0..1023 float4 slots
            int r = idx >> 4;                   // 0..63
            int k = (idx & 15) * 4;             // 0..60
            int gr = row0 + r;
            float4 v = (gr < M) ? *(const float4*)(A + (long)gr * K + k0 + k)
                                : make_float4(0.f, 0.f, 0.f, 0.f);
            As[(k + 0) * 65 + r] = v.x;
            As[(k + 1) * 65 + r] = v.y;
            As[(k + 2) * 65 + r] = v.z;
            As[(k + 3) * 65 + r] = v.w;
        }
        // stage W
        #pragma unroll
        for (int i = 0; i < 4; i++) {
            int idx = threadIdx.x + i * 256;    // 0..1023 float4 slots
            int k = idx >> 4;
            int c = (idx & 15) * 4;
            float4 v = *(const float4*)(W + (long)(k0 + k) * NC + col0 + c);
            *(float4*)&Ws[k * 64 + c] = v;
        }
        __syncthreads();
        #pragma unroll
        for (int k = 0; k < 64; k++) {
            float a0 = As[k * 65 + ty * 4 + 0];
            float a1 = As[k * 65 + ty * 4 + 1];
            float a2 = As[k * 65 + ty * 4 + 2];
            float a3 = As[k * 65 + ty * 4 + 3];
            float4 w = *(const float4*)&Ws[k * 64 + tx * 4];
            acc[0][0] += a0 * w.x; acc[0][1] += a0 * w.y; acc[0][2] += a0 * w.z; acc[0][3] += a0 * w.w;
            acc[1][0] += a1 * w.x; acc[1][1] += a1 * w.y; acc[1][2] += a1 * w.z; acc[1][3] += a1 * w.w;
            acc[2][0] += a2 * w.x; acc[2][1] += a2 * w.y; acc[2][2] += a2 * w.z; acc[2][3] += a2 * w.w;
            acc[3][0] += a3 * w.x; acc[3][1] += a3 * w.y; acc[3][2] += a3 * w.z; acc[3][3] += a3 * w.w;
        }
        __syncthreads();
    }
    float4 bv = make_float4(0.f, 0.f, 0.f, 0.f);
    if (BIAS) bv = *(const float4*)(bias + col0 + tx * 4);
    #pragma unroll
    for (int i = 0; i < 4; i++) {
        int gr = row0 + ty * 4 + i;
        if (gr >= M) continue;
        float4 o = make_float4(acc[i][0] + bv.x, acc[i][1] + bv.y,
                               acc[i][2] + bv.z, acc[i][3] + bv.w);
        if (RELU) {
            o.x = fmaxf(o.x, 0.f); o.y = fmaxf(o.y, 0.f);
            o.z = fmaxf(o.z, 0.f); o.w = fmaxf(o.w, 0.f);
        }
        *(float4*)(out + (long)gr * NC + col0 + tx * 4) = o;
    }
}

// dual-(A,W) tiled GEMM: out = A1@W1v + A2@W2v + bias   (K = NC = 64)
__global__ __launch_bounds__(256) void gemm2_tile_kernel(
        const float* __restrict__ A1, const float* __restrict__ W1v,
        const float* __restrict__ A2, const float* __restrict__ W2v,
        const float* __restrict__ bias, float* __restrict__ out, int M) {
    __shared__ float As[64 * 65];
    __shared__ float Ws[64 * 64];
    int row0 = blockIdx.x * 64;
    int tx = threadIdx.x & 15, ty = threadIdx.x >> 4;
    float acc[4][4] = {};
    #pragma unroll
    for (int p = 0; p < 2; p++) {
        const float* A = p ? A2 : A1;
        const float* W = p ? W2v : W1v;
        #pragma unroll
        for (int i = 0; i < 4; i++) {
            int idx = threadIdx.x * 4 + i;
            int r = idx >> 4;
            int k = (idx & 15) * 4;
            int gr = row0 + r;
            float4 v = (gr < M) ? *(const float4*)(A + (long)gr * 64 + k)
                                : make_float4(0.f, 0.f, 0.f, 0.f);
            As[(k + 0) * 65 + r] = v.x;
            As[(k + 1) * 65 + r] = v.y;
            As[(k + 2) * 65 + r] = v.z;
            As[(k + 3) * 65 + r] = v.w;
        }
        #pragma unroll
        for (int i = 0; i < 4; i++) {
            int idx = threadIdx.x + i * 256;
            int k = idx >> 4;
            int c = (idx & 15) * 4;
            *(float4*)&Ws[k * 64 + c] = *(const float4*)(W + (long)k * 64 + c);
        }
        __syncthreads();
        #pragma unroll
        for (int k = 0; k < 64; k++) {
            float a0 = As[k * 65 + ty * 4 + 0];
            float a1 = As[k * 65 + ty * 4 + 1];
            float a2 = As[k * 65 + ty * 4 + 2];
            float a3 = As[k * 65 + ty * 4 + 3];
            float4 w = *(const float4*)&Ws[k * 64 + tx * 4];
            acc[0][0] += a0 * w.x; acc[0][1] += a0 * w.y; acc[0][2] += a0 * w.z; acc[0][3] += a0 * w.w;
            acc[1][0] += a1 * w.x; acc[1][1] += a1 * w.y; acc[1][2] += a1 * w.z; acc[1][3] += a1 * w.w;
            acc[2][0] += a2 * w.x; acc[2][1] += a2 * w.y; acc[2][2] += a2 * w.z; acc[2][3] += a2 * w.w;
            acc[3][0] += a3 * w.x; acc[3][1] += a3 * w.y; acc[3][2] += a3 * w.z; acc[3][3] += a3 * w.w;
        }
        __syncthreads();
    }
    float4 bv = *(const float4*)(bias + tx * 4);
    #pragma unroll
    for (int i = 0; i < 4; i++) {
        int gr = row0 + ty * 4 + i;
        if (gr >= M) continue;
        float4 o = make_float4(acc[i][0] + bv.x, acc[i][1] + bv.y,
                               acc[i][2] + bv.z, acc[i][3] + bv.w);
        *(float4*)(out + (long)gr * 64 + tx * 4) = o;
    }
}

// ---------------- GCN node gather (fused norm + self-loop + bias + relu) ----
__global__ __launch_bounds__(64) void gcn_node_kernel(const float* __restrict__ b1) {
    int n = blockIdx.x;
    int c = threadIdx.x;
    int beg = g_rowptr[n], end = g_rowptr[n + 1];
    float acc0 = 0.f, acc1 = 0.f, acc2 = 0.f, acc3 = 0.f;
    int j = beg;
    for (; j + 4 <= end; j += 4) {
        int s0 = g_csrc[j], s1 = g_csrc[j + 1], s2 = g_csrc[j + 2], s3 = g_csrc[j + 3];
        float w0 = g_dinv[s0], w1 = g_dinv[s1], w2 = g_dinv[s2], w3 = g_dinv[s3];
        float v0 = g_h1[s0 * HDIM + c], v1 = g_h1[s1 * HDIM + c];
        float v2 = g_h1[s2 * HDIM + c], v3 = g_h1[s3 * HDIM + c];
        acc0 += w0 * v0; acc1 += w1 * v1; acc2 += w2 * v2; acc3 += w3 * v3;
    }
    for (; j < end; j++) {
        int s0 = g_csrc[j];
        acc0 += g_dinv[s0] * g_h1[s0 * HDIM + c];
    }
    float dn = g_dinv[n];
    float v = dn * (acc0 + acc1 + acc2 + acc3) + dn * dn * g_h1[n * HDIM + c] + b1[c];
    g_hA[n * HDIM + c] = fmaxf(v, 0.f);
}

// ---------------- GAT per-node attention scores ------------------------------
__global__ void att_kernel(const float* __restrict__ att_src,
                           const float* __restrict__ att_dst, int N) {
    int warp = (blockIdx.x * blockDim.x + threadIdx.x) >> 5;
    int lane = threadIdx.x & 31;
    if (warp >= N) return;
    const float* hg = g_hg + (long)warp * (NHEADS * HDIM);
    #pragma unroll
    for (int h = 0; h < NHEADS; h++) {
        float v1 = hg[h * HDIM + lane], v2 = hg[h * HDIM + 32 + lane];
        float s = v1 * att_src[h * HDIM + lane] + v2 * att_src[h * HDIM + 32 + lane];
        float d = v1 * att_dst[h * HDIM + lane] + v2 * att_dst[h * HDIM + 32 + lane];
        #pragma unroll
        for (int o = 16; o; o >>= 1) {
            s += __shfl_xor_sync(0xffffffffu, s, o);
            d += __shfl_xor_sync(0xffffffffu, d, o);
        }
        if (lane == 0) { g_asrc[warp * NHEADS + h] = s; g_adst[warp * NHEADS + h] = d; }
    }
}

// ---------------- GAT node: softmax over in-edges + weighted gather ----------
__global__ __launch_bounds__(64) void gat_node_kernel(const float* __restrict__ bg) {
    __shared__ float smax[NHEADS];
    __shared__ float sinvden[NHEADS];
    __shared__ float salpha_self[NHEADS];
    __shared__ float redbuf[2 * NHEADS];
    __shared__ float s_alpha[16 * NHEADS];
    __shared__ int   s_src[16];

    int n = blockIdx.x;
    int tid = threadIdx.x;
    int lane = tid & 31, wid = tid >> 5;
    int beg = g_rowptr[n], end = g_rowptr[n + 1];

    float4 ad = *(const float4*)&g_adst[n * NHEADS];
    float4 asn = *(const float4*)&g_asrc[n * NHEADS];
    float eself[NHEADS] = {
        lrelu02(asn.x + ad.x), lrelu02(asn.y + ad.y),
        lrelu02(asn.z + ad.z), lrelu02(asn.w + ad.w) };

    // pass 1: per-head max
    float m[NHEADS] = { eself[0], eself[1], eself[2], eself[3] };
    for (int j = beg + tid; j < end; j += 64) {
        int s = g_csrc[j];
        float4 as = *(const float4*)&g_asrc[s * NHEADS];
        m[0] = fmaxf(m[0], lrelu02(as.x + ad.x));
        m[1] = fmaxf(m[1], lrelu02(as.y + ad.y));
        m[2] = fmaxf(m[2], lrelu02(as.z + ad.z));
        m[3] = fmaxf(m[3], lrelu02(as.w + ad.w));
    }
    #pragma unroll
    for (int o = 16; o; o >>= 1)
        #pragma unroll
        for (int h = 0; h < NHEADS; h++)
            m[h] = fmaxf(m[h], __shfl_xor_sync(0xffffffffu, m[h], o));
    if (lane == 0)
        #pragma unroll
        for (int h = 0; h < NHEADS; h++) redbuf[wid * NHEADS + h] = m[h];
    __syncthreads();
    if (tid < NHEADS) smax[tid] = fmaxf(redbuf[tid], redbuf[NHEADS + tid]);
    __syncthreads();

    // pass 2: per-head denominator
    float d[NHEADS] = { 0.f, 0.f, 0.f, 0.f };
    for (int j = beg + tid; j < end; j += 64) {
        int s = g_csrc[j];
        float4 as = *(const float4*)&g_asrc[s * NHEADS];
        d[0] += __expf(lrelu02(as.x + ad.x) - smax[0]);
        d[1] += __expf(lrelu02(as.y + ad.y) - smax[1]);
        d[2] += __expf(lrelu02(as.z + ad.z) - smax[2]);
        d[3] += __expf(lrelu02(as.w + ad.w) - smax[3]);
    }
    #pragma unroll
    for (int o = 16; o; o >>= 1)
        #pragma unroll
        for (int h = 0; h < NHEADS; h++)
            d[h] += __shfl_xor_sync(0xffffffffu, d[h], o);
    if (lane == 0)
        #pragma unroll
        for (int h = 0; h < NHEADS; h++) redbuf[wid * NHEADS + h] = d[h];
    __syncthreads();
    if (tid < NHEADS) {
        float exs = __expf(eself[tid] - smax[tid]);
        float den = redbuf[tid] + redbuf[NHEADS + tid] + exs;
        float inv = 1.f / den;
        sinvden[tid] = inv;
        salpha_self[tid] = exs * inv;
    }
    __syncthreads();

    // pass 3: fixed-16 chunk staging (zero-padded) + fully-unrolled gather
    int c = tid;
    float acc = 0.f;
    for (int base = beg; base < end; base += 16) {
        {
            int jj = tid >> 2, h = tid & 3;   // tid<64 covers all 16x4 slots
            int j = base + jj;
            float alpha = 0.f;
            int s = 0;
            if (j < end) {
                s = g_csrc[j];
                float av = g_asrc[s * NHEADS + h];
                float dv = ((const float*)&ad)[h];
                alpha = __expf(lrelu02(av + dv) - smax[h]) * sinvden[h];
            }
            s_alpha[jj * NHEADS + h] = alpha;
            if (h == 0) s_src[jj] = s;
        }
        __syncthreads();
        #pragma unroll
        for (int jj = 0; jj < 16; jj++) {
            int s = s_src[jj];
            const float* hgp = g_hg + (long)s * (NHEADS * HDIM) + c;
            acc += s_alpha[jj * NHEADS + 0] * hgp[0]
                 + s_alpha[jj * NHEADS + 1] * hgp[HDIM]
                 + s_alpha[jj * NHEADS + 2] * hgp[2 * HDIM]
                 + s_alpha[jj * NHEADS + 3] * hgp[3 * HDIM];
        }
        __syncthreads();
    }
    {
        const float* hgp = g_hg + (long)n * (NHEADS * HDIM) + c;
        acc += salpha_self[0] * hgp[0]
             + salpha_self[1] * hgp[HDIM]
             + salpha_self[2] * hgp[2 * HDIM]
             + salpha_self[3] * hgp[3 * HDIM];
    }
    g_hB[n * HDIM + c] = fmaxf(0.25f * acc + bg[c], 0.f);
}

// ---------------- SAGE node mean gather -------------------------------------
__global__ __launch_bounds__(64) void sage_node_kernel() {
    int n = blockIdx.x;
    int c = threadIdx.x;
    int beg = g_rowptr[n], end = g_rowptr[n + 1];
    float acc0 = 0.f, acc1 = 0.f, acc2 = 0.f, acc3 = 0.f;
    int j = beg;
    for (; j + 4 <= end; j += 4) {
        int s0 = g_csrc[j], s1 = g_csrc[j + 1], s2 = g_csrc[j + 2], s3 = g_csrc[j + 3];
        acc0 += g_hB[s0 * HDIM + c];
        acc1 += g_hB[s1 * HDIM + c];
        acc2 += g_hB[s2 * HDIM + c];
        acc3 += g_hB[s3 * HDIM + c];
    }
    for (; j < end; j++) acc0 += g_hB[g_csrc[j] * HDIM + c];
    float inv = 1.f / fmaxf((float)(end - beg), 1.f);
    g_macc[n * HDIM + c] = (acc0 + acc1 + acc2 + acc3) * inv;
}

// ---------------- heads -----------------------------------------------------
__global__ void heads_kernel(const float* __restrict__ emb,
        const float* __restrict__ a1w, const float* __restrict__ a1b,
        const float* __restrict__ a2w, const float* __restrict__ a2b,
        const float* __restrict__ r1w, const float* __restrict__ r1b,
        const float* __restrict__ r2w, const float* __restrict__ r2b,
        float* __restrict__ anomaly, float* __restrict__ risk, int N) {
    int warp = (blockIdx.x * blockDim.x + threadIdx.x) >> 5;
    int lane = threadIdx.x & 31;
    if (warp >= N) return;
    const float* e = emb + (long)warp * HDIM;
    float sa = a1b[lane], sr = r1b[lane];
    #pragma unroll 8
    for (int k = 0; k < HDIM; k++) {
        float ev = e[k];
        sa += ev * a1w[k * 32 + lane];
        sr += ev * r1w[k * 32 + lane];
    }
    sa = fmaxf(sa, 0.f) * a2w[lane];
    sr = fmaxf(sr, 0.f) * r2w[lane];
    #pragma unroll
    for (int o = 16; o; o >>= 1) {
        sa += __shfl_xor_sync(0xffffffffu, sa, o);
        sr += __shfl_xor_sync(0xffffffffu, sr, o);
    }
    if (lane == 0) {
        anomaly[warp] = 1.f / (1.f + __expf(-(sa + a2b[0])));
        risk[warp]    = 1.f / (1.f + __expf(-(sr + r2b[0])));
    }
}

// ---------------- launch ----------------------------------------------------
extern "C" void kernel_launch(void* const* d_in, const int* in_sizes, int n_in,
                              void* d_out, int out_size) {
    const float* x    = (const float*)d_in[0];
    const void*  eidx = d_in[1];
    const float* W1   = (const float*)d_in[2];
    const float* b1   = (const float*)d_in[3];
    const float* Wg   = (const float*)d_in[4];
    const float *att_src, *att_dst, *bg;
    if (in_sizes[5] == NHEADS * HDIM) {        // dict order
        att_src = (const float*)d_in[5];
        att_dst = (const float*)d_in[6];
        bg      = (const float*)d_in[7];
    } else {                                    // signature order
        bg      = (const float*)d_in[5];
        att_src = (const float*)d_in[6];
        att_dst = (const float*)d_in[7];
    }
    const float* Wl  = (const float*)d_in[8];
    const float* bl  = (const float*)d_in[9];
    const float* Wr  = (const float*)d_in[10];
    const float* a1w = (const float*)d_in[11];
    const float* a1b = (const float*)d_in[12];
    const float* a2w = (const float*)d_in[13];
    const float* a2b = (const float*)d_in[14];
    const float* r1w = (const float*)d_in[15];
    const float* r1b = (const float*)d_in[16];
    const float* r2w = (const float*)d_in[17];
    const float* r2b = (const float*)d_in[18];

    int N = in_sizes[0] / FIN;
    int E = in_sizes[1] / 2;

    float* out_emb = (float*)d_out;
    float* out_an  = out_emb + (long)N * HDIM;
    float* out_rk  = out_an + N;

    void* p;
    cudaGetSymbolAddress(&p, g_indeg);  cudaMemsetAsync(p, 0, (size_t)N * 4);
    cudaGetSymbolAddress(&p, g_cursor); cudaMemsetAsync(p, 0, (size_t)N * 4);

    detect_kernel<<<1, 256>>>((const unsigned*)eidx);
    convert_deg_kernel<<<(E + 255) / 256, 256>>>(eidx, E);
    scan_kernel<<<1, 1024>>>(N);
    fill_kernel<<<(E + 255) / 256, 256>>>(E);

    int mtiles = (N + 63) / 64;

    // GCN
    {
        void* h1; cudaGetSymbolAddress(&h1, g_h1);
        gemm_tile_kernel<FIN, false, false><<<dim3(mtiles, 1), 256>>>(
            x, W1, nullptr, (float*)h1, N, HDIM);
    }
    gcn_node_kernel<<<N, 64>>>(b1);

    // GAT
    {
        void* hA; cudaGetSymbolAddress(&hA, g_hA);
        void* hg; cudaGetSymbolAddress(&hg, g_hg);
        gemm_tile_kernel<HDIM, false, false><<<dim3(mtiles, NHEADS), 256>>>(
            (const float*)hA, Wg, nullptr, (float*)hg, N, NHEADS * HDIM);
    }
    att_kernel<<<(N * 32 + 255) / 256, 256>>>(att_src, att_dst, N);
    gat_node_kernel<<<N, 64>>>(bg);

    // SAGE
    sage_node_kernel<<<N, 64>>>();
    {
        void* macc; cudaGetSymbolAddress(&macc, g_macc);
        void* hB;   cudaGetSymbolAddress(&hB, g_hB);
        gemm2_tile_kernel<<<mtiles, 256>>>(
            (const float*)macc, Wl, (const float*)hB, Wr, bl, out_emb, N);
    }

    // heads
    heads_kernel<<<(N * 32 + 255) / 256, 256>>>(
        out_emb, a1w, a1b, a2w, a2b, r1w, r1b, r2w, r2b, out_an, out_rk, N);
}

// round 5
// speedup vs baseline: 2.0172x; 1.0884x over previous
#include <cuda_runtime.h>
#include <math.h>

#define NMAX   50000
#define EMAX   800000
#define HDIM   64
#define NHEADS 4
#define FIN    128

// ---------------- scratch (device globals; no allocation allowed) ----------
__device__ int      g_flag;                  // 1 => edge_index is int64
__device__ int      g_row[EMAX];
__device__ int      g_col[EMAX];
__device__ int      g_indeg[NMAX];
__device__ int      g_rowptr[NMAX + 1];
__device__ int      g_cursor[NMAX];
__device__ int      g_csrc[EMAX];            // CSR: src node per in-edge, grouped by dst
__device__ float    g_dinv[NMAX];
__device__ float    g_h1  [NMAX*HDIM];       // x @ W1
__device__ float    g_hA  [NMAX*HDIM];       // post-GCN (relu)
__device__ float    g_hg  [NMAX*NHEADS*HDIM];// hA @ Wg  (layout [n][h][c])
__device__ float    g_asrc[NMAX*NHEADS];
__device__ float    g_adst[NMAX*NHEADS];
__device__ float    g_hB  [NMAX*HDIM];       // post-GAT (relu)
__device__ float    g_macc[NMAX*HDIM];       // SAGE mean agg

__device__ __forceinline__ float lrelu02(float x) { return x >= 0.f ? x : 0.2f * x; }

__device__ __forceinline__ unsigned f2tf32(float f) {
    unsigned r;
    asm("cvt.rna.tf32.f32 %0, %1;" : "=r"(r) : "f"(f));
    return r;
}

// ---------------- dtype detection ------------------------------------------
__global__ void detect_kernel(const unsigned* __restrict__ words) {
    __shared__ int nz;
    if (threadIdx.x == 0) nz = 0;
    __syncthreads();
    unsigned w = words[threadIdx.x * 2 + 1];
    if (w != 0u) atomicAdd(&nz, 1);
    __syncthreads();
    if (threadIdx.x == 0) g_flag = (nz == 0) ? 1 : 0;
}

// convert edge index to int32 and accumulate in-degree
__global__ void convert_deg_kernel(const void* __restrict__ eidx, int E) {
    int i = blockIdx.x * blockDim.x + threadIdx.x;
    if (i >= E) return;
    int r, c;
    if (g_flag) {
        const long long* p = (const long long*)eidx;
        r = (int)p[i]; c = (int)p[i + E];
    } else {
        const int* p = (const int*)eidx;
        r = p[i]; c = p[i + E];
    }
    g_row[i] = r; g_col[i] = c;
    atomicAdd(&g_indeg[c], 1);
}

// exclusive scan of g_indeg -> g_rowptr; also writes g_dinv
__global__ void scan_kernel(int N) {
    __shared__ int sums[1024];
    int tid = threadIdx.x;
    int chunk = (N + 1023) / 1024;
    int b = tid * chunk, e = min(b + chunk, N);
    int s = 0;
    for (int i = b; i < e; i++) s += g_indeg[i];
    sums[tid] = s;
    __syncthreads();
    for (int off = 1; off < 1024; off <<= 1) {
        int v = (tid >= off) ? sums[tid - off] : 0;
        __syncthreads();
        sums[tid] += v;
        __syncthreads();
    }
    int run = (tid > 0) ? sums[tid - 1] : 0;
    for (int i = b; i < e; i++) {
        int d = g_indeg[i];
        g_rowptr[i] = run; run += d;
        g_dinv[i] = rsqrtf((float)(d + 1));
    }
    if (tid == 1023) g_rowptr[N] = sums[1023];
}

__global__ void fill_kernel(int E) {
    int i = blockIdx.x * blockDim.x + threadIdx.x;
    if (i >= E) return;
    int c = g_col[i];
    int pos = g_rowptr[c] + atomicAdd(&g_cursor[c], 1);
    g_csrc[pos] = g_row[i];
}

// ===================== tf32 tensor-core GEMM ================================
// out[M, NC] = A[M, K] @ W[K, NC]  (+ optional second pair, bias, relu)
// Block: 256 threads (8 warps). Block tile: 128 rows x 64 cols (col0 = 64*blockIdx.y).
// Warp w: rows 16w..16w+15, cols 0..63 (8 m16n8 tiles). K chunked by 32.
//
// SMEM layouts use a paired-k ordering kp(k8) = (k8&3)*2 + (k8>>2) so that the
// per-fragment loads (cols c & c+4 for A; rows k & k+4 for B) are LDS.64.
#define KP(k8) (((k8) & 3) * 2 + ((k8) >> 2))

struct GemmSmem {
    unsigned As[128 * 36];   // [row][kstep*8 + kp], tf32 bits
    unsigned Wt[64 * 36];    // [col][kstep*8 + kp], tf32 bits
};

// stage one 128x32 A chunk (rows row0.., k offset k0) into s->As
__device__ __forceinline__ void stage_A(GemmSmem* s, const float* __restrict__ A,
                                        int row0, int k0, int K, int M) {
    #pragma unroll
    for (int i = 0; i < 4; i++) {
        int idx = threadIdx.x + i * 256;      // 0..1023 float4 slots
        int r = idx >> 3;                      // 0..127
        int f4 = idx & 7;                      // 8 float4 per 32-float row
        int gr = row0 + r;
        float4 v = (gr < M) ? *(const float4*)(A + (long)gr * K + k0 + f4 * 4)
                            : make_float4(0.f, 0.f, 0.f, 0.f);
        unsigned* dst = s->As + r * 36 + (f4 >> 1) * 8 + (f4 & 1);
        dst[0] = f2tf32(v.x);
        dst[2] = f2tf32(v.y);
        dst[4] = f2tf32(v.z);
        dst[6] = f2tf32(v.w);
    }
}

// stage one 32x64 W chunk (k offset k0, col offset col0, row stride NC) into s->Wt
__device__ __forceinline__ void stage_W(GemmSmem* s, const float* __restrict__ W,
                                        int k0, int col0, int NC) {
    #pragma unroll
    for (int i = 0; i < 2; i++) {
        int idx = threadIdx.x + i * 256;      // 0..511 float4 slots
        int kl = idx >> 4;                     // 0..31
        int f4 = idx & 15;                     // 16 float4 per 64-col row
        float4 v = *(const float4*)(W + (long)(k0 + kl) * NC + col0 + f4 * 4);
        int kpos = (kl >> 3) * 8 + KP(kl & 7);
        s->Wt[(f4 * 4 + 0) * 36 + kpos] = f2tf32(v.x);
        s->Wt[(f4 * 4 + 1) * 36 + kpos] = f2tf32(v.y);
        s->Wt[(f4 * 4 + 2) * 36 + kpos] = f2tf32(v.z);
        s->Wt[(f4 * 4 + 3) * 36 + kpos] = f2tf32(v.w);
    }
}

__device__ __forceinline__ void mma_chunk(GemmSmem* s, int warp, int lane, float c[8][4]) {
    int g = lane >> 2, t = lane & 3;
    #pragma unroll
    for (int ks = 0; ks < 4; ks++) {
        unsigned a0, a1, a2, a3;
        {
            const unsigned* p1 = s->As + (warp * 16 + g) * 36 + ks * 8 + t * 2;
            const unsigned* p2 = p1 + 8 * 36;
            uint2 lo = *(const uint2*)p1;      // (a0, a2)
            uint2 hi = *(const uint2*)p2;      // (a1, a3)
            a0 = lo.x; a2 = lo.y; a1 = hi.x; a3 = hi.y;
        }
        #pragma unroll
        for (int nt = 0; nt < 8; nt++) {
            uint2 b = *(const uint2*)(s->Wt + (nt * 8 + g) * 36 + ks * 8 + t * 2);
            asm volatile(
                "mma.sync.aligned.m16n8k8.row.col.f32.tf32.tf32.f32 "
                "{%0,%1,%2,%3}, {%4,%5,%6,%7}, {%8,%9}, {%0,%1,%2,%3};"
                : "+f"(c[nt][0]), "+f"(c[nt][1]), "+f"(c[nt][2]), "+f"(c[nt][3])
                : "r"(a0), "r"(a1), "r"(a2), "r"(a3), "r"(b.x), "r"(b.y));
        }
    }
}

template<int K, bool BIAS, bool RELU>
__global__ __launch_bounds__(256) void gemm_tf32_kernel(
        const float* __restrict__ A, const float* __restrict__ W,
        const float* __restrict__ bias, float* __restrict__ out,
        int M, int NC) {
    __shared__ GemmSmem s;
    int row0 = blockIdx.x * 128;
    int col0 = blockIdx.y * 64;
    int warp = threadIdx.x >> 5, lane = threadIdx.x & 31;
    float c[8][4] = {};
    #pragma unroll
    for (int k0 = 0; k0 < K; k0 += 32) {
        stage_A(&s, A, row0, k0, K, M);
        stage_W(&s, W, k0, col0, NC);
        __syncthreads();
        mma_chunk(&s, warp, lane, c);
        __syncthreads();
    }
    int g = lane >> 2, t = lane & 3;
    int gr0 = row0 + warp * 16 + g;
    #pragma unroll
    for (int nt = 0; nt < 8; nt++) {
        int col = col0 + nt * 8 + t * 2;
        float bx = 0.f, by = 0.f;
        if (BIAS) { bx = bias[col]; by = bias[col + 1]; }
        float2 v0 = make_float2(c[nt][0] + bx, c[nt][1] + by);
        float2 v1 = make_float2(c[nt][2] + bx, c[nt][3] + by);
        if (RELU) {
            v0.x = fmaxf(v0.x, 0.f); v0.y = fmaxf(v0.y, 0.f);
            v1.x = fmaxf(v1.x, 0.f); v1.y = fmaxf(v1.y, 0.f);
        }
        if (gr0 < M)     *(float2*)(out + (long)gr0 * NC + col) = v0;
        if (gr0 + 8 < M) *(float2*)(out + (long)(gr0 + 8) * NC + col) = v1;
    }
}

// dual-pair tf32 GEMM: out = A1@W1v + A2@W2v + bias   (K = NC = 64)
__global__ __launch_bounds__(256) void gemm2_tf32_kernel(
        const float* __restrict__ A1, const float* __restrict__ W1v,
        const float* __restrict__ A2, const float* __restrict__ W2v,
        const float* __restrict__ bias, float* __restrict__ out, int M) {
    __shared__ GemmSmem s;
    int row0 = blockIdx.x * 128;
    int warp = threadIdx.x >> 5, lane = threadIdx.x & 31;
    float c[8][4] = {};
    #pragma unroll
    for (int p = 0; p < 2; p++) {
        const float* A = p ? A2 : A1;
        const float* W = p ? W2v : W1v;
        #pragma unroll
        for (int k0 = 0; k0 < 64; k0 += 32) {
            stage_A(&s, A, row0, k0, 64, M);
            stage_W(&s, W, k0, 0, 64);
            __syncthreads();
            mma_chunk(&s, warp, lane, c);
            __syncthreads();
        }
    }
    int g = lane >> 2, t = lane & 3;
    int gr0 = row0 + warp * 16 + g;
    #pragma unroll
    for (int nt = 0; nt < 8; nt++) {
        int col = nt * 8 + t * 2;
        float bx = bias[col], by = bias[col + 1];
        if (gr0 < M)
            *(float2*)(out + (long)gr0 * 64 + col) =
                make_float2(c[nt][0] + bx, c[nt][1] + by);
        if (gr0 + 8 < M)
            *(float2*)(out + (long)(gr0 + 8) * 64 + col) =
                make_float2(c[nt][2] + bx, c[nt][3] + by);
    }
}

// ---------------- GCN node gather (fused norm + self-loop + bias + relu) ----
__global__ __launch_bounds__(64) void gcn_node_kernel(const float* __restrict__ b1) {
    int n = blockIdx.x;
    int c = threadIdx.x;
    int beg = g_rowptr[n], end = g_rowptr[n + 1];
    float acc0 = 0.f, acc1 = 0.f, acc2 = 0.f, acc3 = 0.f;
    int j = beg;
    for (; j + 4 <= end; j += 4) {
        int s0 = g_csrc[j], s1 = g_csrc[j + 1], s2 = g_csrc[j + 2], s3 = g_csrc[j + 3];
        float w0 = g_dinv[s0], w1 = g_dinv[s1], w2 = g_dinv[s2], w3 = g_dinv[s3];
        float v0 = g_h1[s0 * HDIM + c], v1 = g_h1[s1 * HDIM + c];
        float v2 = g_h1[s2 * HDIM + c], v3 = g_h1[s3 * HDIM + c];
        acc0 += w0 * v0; acc1 += w1 * v1; acc2 += w2 * v2; acc3 += w3 * v3;
    }
    for (; j < end; j++) {
        int s0 = g_csrc[j];
        acc0 += g_dinv[s0] * g_h1[s0 * HDIM + c];
    }
    float dn = g_dinv[n];
    float v = dn * (acc0 + acc1 + acc2 + acc3) + dn * dn * g_h1[n * HDIM + c] + b1[c];
    g_hA[n * HDIM + c] = fmaxf(v, 0.f);
}

// ---------------- GAT per-node attention scores ------------------------------
__global__ void att_kernel(const float* __restrict__ att_src,
                           const float* __restrict__ att_dst, int N) {
    int warp = (blockIdx.x * blockDim.x + threadIdx.x) >> 5;
    int lane = threadIdx.x & 31;
    if (warp >= N) return;
    const float* hg = g_hg + (long)warp * (NHEADS * HDIM);
    #pragma unroll
    for (int h = 0; h < NHEADS; h++) {
        float v1 = hg[h * HDIM + lane], v2 = hg[h * HDIM + 32 + lane];
        float s = v1 * att_src[h * HDIM + lane] + v2 * att_src[h * HDIM + 32 + lane];
        float d = v1 * att_dst[h * HDIM + lane] + v2 * att_dst[h * HDIM + 32 + lane];
        #pragma unroll
        for (int o = 16; o; o >>= 1) {
            s += __shfl_xor_sync(0xffffffffu, s, o);
            d += __shfl_xor_sync(0xffffffffu, d, o);
        }
        if (lane == 0) { g_asrc[warp * NHEADS + h] = s; g_adst[warp * NHEADS + h] = d; }
    }
}

// ---------------- GAT node: softmax over in-edges + weighted gather ----------
__global__ __launch_bounds__(64) void gat_node_kernel(const float* __restrict__ bg) {
    __shared__ float smax[NHEADS];
    __shared__ float sinvden[NHEADS];
    __shared__ float salpha_self[NHEADS];
    __shared__ float redbuf[2 * NHEADS];
    __shared__ float s_alpha[16 * NHEADS];
    __shared__ int   s_src[16];

    int n = blockIdx.x;
    int tid = threadIdx.x;
    int lane = tid & 31, wid = tid >> 5;
    int beg = g_rowptr[n], end = g_rowptr[n + 1];

    float4 ad = *(const float4*)&g_adst[n * NHEADS];
    float4 asn = *(const float4*)&g_asrc[n * NHEADS];
    float eself[NHEADS] = {
        lrelu02(asn.x + ad.x), lrelu02(asn.y + ad.y),
        lrelu02(asn.z + ad.z), lrelu02(asn.w + ad.w) };

    // pass 1: per-head max
    float m[NHEADS] = { eself[0], eself[1], eself[2], eself[3] };
    for (int j = beg + tid; j < end; j += 64) {
        int s = g_csrc[j];
        float4 as = *(const float4*)&g_asrc[s * NHEADS];
        m[0] = fmaxf(m[0], lrelu02(as.x + ad.x));
        m[1] = fmaxf(m[1], lrelu02(as.y + ad.y));
        m[2] = fmaxf(m[2], lrelu02(as.z + ad.z));
        m[3] = fmaxf(m[3], lrelu02(as.w + ad.w));
    }
    #pragma unroll
    for (int o = 16; o; o >>= 1)
        #pragma unroll
        for (int h = 0; h < NHEADS; h++)
            m[h] = fmaxf(m[h], __shfl_xor_sync(0xffffffffu, m[h], o));
    if (lane == 0)
        #pragma unroll
        for (int h = 0; h < NHEADS; h++) redbuf[wid * NHEADS + h] = m[h];
    __syncthreads();
    if (tid < NHEADS) smax[tid] = fmaxf(redbuf[tid], redbuf[NHEADS + tid]);
    __syncthreads();

    // pass 2: per-head denominator
    float d[NHEADS] = { 0.f, 0.f, 0.f, 0.f };
    for (int j = beg + tid; j < end; j += 64) {
        int s = g_csrc[j];
        float4 as = *(const float4*)&g_asrc[s * NHEADS];
        d[0] += __expf(lrelu02(as.x + ad.x) - smax[0]);
        d[1] += __expf(lrelu02(as.y + ad.y) - smax[1]);
        d[2] += __expf(lrelu02(as.z + ad.z) - smax[2]);
        d[3] += __expf(lrelu02(as.w + ad.w) - smax[3]);
    }
    #pragma unroll
    for (int o = 16; o; o >>= 1)
        #pragma unroll
        for (int h = 0; h < NHEADS; h++)
            d[h] += __shfl_xor_sync(0xffffffffu, d[h], o);
    if (lane == 0)
        #pragma unroll
        for (int h = 0; h < NHEADS; h++) redbuf[wid * NHEADS + h] = d[h];
    __syncthreads();
    if (tid < NHEADS) {
        float exs = __expf(eself[tid] - smax[tid]);
        float den = redbuf[tid] + redbuf[NHEADS + tid] + exs;
        float inv = 1.f / den;
        sinvden[tid] = inv;
        salpha_self[tid] = exs * inv;
    }
    __syncthreads();

    // pass 3: fixed-16 chunk staging (zero-padded) + fully-unrolled gather
    int c = tid;
    float acc = 0.f;
    for (int base = beg; base < end; base += 16) {
        {
            int jj = tid >> 2, h = tid & 3;
            int j = base + jj;
            float alpha = 0.f;
            int s = 0;
            if (j < end) {
                s = g_csrc[j];
                float av = g_asrc[s * NHEADS + h];
                float dv = ((const float*)&ad)[h];
                alpha = __expf(lrelu02(av + dv) - smax[h]) * sinvden[h];
            }
            s_alpha[jj * NHEADS + h] = alpha;
            if (h == 0) s_src[jj] = s;
        }
        __syncthreads();
        #pragma unroll
        for (int jj = 0; jj < 16; jj++) {
            int s = s_src[jj];
            const float* hgp = g_hg + (long)s * (NHEADS * HDIM) + c;
            acc += s_alpha[jj * NHEADS + 0] * hgp[0]
                 + s_alpha[jj * NHEADS + 1] * hgp[HDIM]
                 + s_alpha[jj * NHEADS + 2] * hgp[2 * HDIM]
                 + s_alpha[jj * NHEADS + 3] * hgp[3 * HDIM];
        }
        __syncthreads();
    }
    {
        const float* hgp = g_hg + (long)n * (NHEADS * HDIM) + c;
        acc += salpha_self[0] * hgp[0]
             + salpha_self[1] * hgp[HDIM]
             + salpha_self[2] * hgp[2 * HDIM]
             + salpha_self[3] * hgp[3 * HDIM];
    }
    g_hB[n * HDIM + c] = fmaxf(0.25f * acc + bg[c], 0.f);
}

// ---------------- SAGE node mean gather -------------------------------------
__global__ __launch_bounds__(64) void sage_node_kernel() {
    int n = blockIdx.x;
    int c = threadIdx.x;
    int beg = g_rowptr[n], end = g_rowptr[n + 1];
    float acc0 = 0.f, acc1 = 0.f, acc2 = 0.f, acc3 = 0.f;
    int j = beg;
    for (; j + 4 <= end; j += 4) {
        int s0 = g_csrc[j], s1 = g_csrc[j + 1], s2 = g_csrc[j + 2], s3 = g_csrc[j + 3];
        acc0 += g_hB[s0 * HDIM + c];
        acc1 += g_hB[s1 * HDIM + c];
        acc2 += g_hB[s2 * HDIM + c];
        acc3 += g_hB[s3 * HDIM + c];
    }
    for (; j < end; j++) acc0 += g_hB[g_csrc[j] * HDIM + c];
    float inv = 1.f / fmaxf((float)(end - beg), 1.f);
    g_macc[n * HDIM + c] = (acc0 + acc1 + acc2 + acc3) * inv;
}

// ---------------- heads -----------------------------------------------------
__global__ void heads_kernel(const float* __restrict__ emb,
        const float* __restrict__ a1w, const float* __restrict__ a1b,
        const float* __restrict__ a2w, const float* __restrict__ a2b,
        const float* __restrict__ r1w, const float* __restrict__ r1b,
        const float* __restrict__ r2w, const float* __restrict__ r2b,
        float* __restrict__ anomaly, float* __restrict__ risk, int N) {
    int warp = (blockIdx.x * blockDim.x + threadIdx.x) >> 5;
    int lane = threadIdx.x & 31;
    if (warp >= N) return;
    const float* e = emb + (long)warp * HDIM;
    float sa = a1b[lane], sr = r1b[lane];
    #pragma unroll 8
    for (int k = 0; k < HDIM; k++) {
        float ev = e[k];
        sa += ev * a1w[k * 32 + lane];
        sr += ev * r1w[k * 32 + lane];
    }
    sa = fmaxf(sa, 0.f) * a2w[lane];
    sr = fmaxf(sr, 0.f) * r2w[lane];
    #pragma unroll
    for (int o = 16; o; o >>= 1) {
        sa += __shfl_xor_sync(0xffffffffu, sa, o);
        sr += __shfl_xor_sync(0xffffffffu, sr, o);
    }
    if (lane == 0) {
        anomaly[warp] = 1.f / (1.f + __expf(-(sa + a2b[0])));
        risk[warp]    = 1.f / (1.f + __expf(-(sr + r2b[0])));
    }
}

// ---------------- launch ----------------------------------------------------
extern "C" void kernel_launch(void* const* d_in, const int* in_sizes, int n_in,
                              void* d_out, int out_size) {
    const float* x    = (const float*)d_in[0];
    const void*  eidx = d_in[1];
    const float* W1   = (const float*)d_in[2];
    const float* b1   = (const float*)d_in[3];
    const float* Wg   = (const float*)d_in[4];
    const float *att_src, *att_dst, *bg;
    if (in_sizes[5] == NHEADS * HDIM) {        // dict order
        att_src = (const float*)d_in[5];
        att_dst = (const float*)d_in[6];
        bg      = (const float*)d_in[7];
    } else {                                    // signature order
        bg      = (const float*)d_in[5];
        att_src = (const float*)d_in[6];
        att_dst = (const float*)d_in[7];
    }
    const float* Wl  = (const float*)d_in[8];
    const float* bl  = (const float*)d_in[9];
    const float* Wr  = (const float*)d_in[10];
    const float* a1w = (const float*)d_in[11];
    const float* a1b = (const float*)d_in[12];
    const float* a2w = (const float*)d_in[13];
    const float* a2b = (const float*)d_in[14];
    const float* r1w = (const float*)d_in[15];
    const float* r1b = (const float*)d_in[16];
    const float* r2w = (const float*)d_in[17];
    const float* r2b = (const float*)d_in[18];

    int N = in_sizes[0] / FIN;
    int E = in_sizes[1] / 2;

    float* out_emb = (float*)d_out;
    float* out_an  = out_emb + (long)N * HDIM;
    float* out_rk  = out_an + N;

    void* p;
    cudaGetSymbolAddress(&p, g_indeg);  cudaMemsetAsync(p, 0, (size_t)N * 4);
    cudaGetSymbolAddress(&p, g_cursor); cudaMemsetAsync(p, 0, (size_t)N * 4);

    detect_kernel<<<1, 256>>>((const unsigned*)eidx);
    convert_deg_kernel<<<(E + 255) / 256, 256>>>(eidx, E);
    scan_kernel<<<1, 1024>>>(N);
    fill_kernel<<<(E + 255) / 256, 256>>>(E);

    int mtiles = (N + 127) / 128;

    // GCN:  h1 = x @ W1   (K=128, NC=64)
    {
        void* h1; cudaGetSymbolAddress(&h1, g_h1);
        gemm_tf32_kernel<FIN, false, false><<<dim3(mtiles, 1), 256>>>(
            x, W1, nullptr, (float*)h1, N, HDIM);
    }
    gcn_node_kernel<<<N, 64>>>(b1);

    // GAT:  hg = hA @ Wg  (K=64, NC=256 via 4 column blocks)
    {
        void* hA; cudaGetSymbolAddress(&hA, g_hA);
        void* hg; cudaGetSymbolAddress(&hg, g_hg);
        gemm_tf32_kernel<HDIM, false, false><<<dim3(mtiles, NHEADS), 256>>>(
            (const float*)hA, Wg, nullptr, (float*)hg, N, NHEADS * HDIM);
    }
    att_kernel<<<(N * 32 + 255) / 256, 256>>>(att_src, att_dst, N);
    gat_node_kernel<<<N, 64>>>(bg);

    // SAGE
    sage_node_kernel<<<N, 64>>>();
    {
        void* macc; cudaGetSymbolAddress(&macc, g_macc);
        void* hB;   cudaGetSymbolAddress(&hB, g_hB);
        gemm2_tf32_kernel<<<mtiles, 256>>>(
            (const float*)macc, Wl, (const float*)hB, Wr, bl, out_emb, N);
    }

    // heads
    heads_kernel<<<(N * 32 + 255) / 256, 256>>>(
        out_emb, a1w, a1b, a2w, a2b, r1w, r1b, r2w, r2b, out_an, out_rk, N);
}